// round 17
// baseline (speedup 1.0000x reference)
#include <cuda_runtime.h>
#include <math.h>

// ---------------------------------------------------------------------------
// ToRGB: out = tanh( (x * s[b]) @ k2d + bias ),  s = (w@affine_w + affine_b)/sqrt(512)
// Fold: keff[b,c,o] = s[b,c] * k2d[c,o]
// CHAMPION body (2 px/warp, f32x2 FMA, tanh.approx, 9-shuffle reduce,
// single-wave 74x8 grid, 4 CTAs/SM) + PDL overlap with unit-0 register
// preload and unit-1 L2 prefetch (depth tuned to the prologue shadow).
// ---------------------------------------------------------------------------

#define B_    8
#define CIN   512
#define WDIM  128
#define COUT  4
#define PIX   (128*128)
#define INV_SQRT_CIN 0.04419417382415922f

#define GRID_X          74               // 74*8 = 592 = 148 SMs * 4 CTAs
#define UNIT_PX         16               // 8 warps * 2 px
#define UNITS_PER_BATCH (PIX / UNIT_PX)  // 1024

typedef unsigned long long u64;

// folded per-batch kernel, PERMUTED (R6 scheme):
// c = lane*4 + j + i*128  ->  idx = (i*4 + j)*32 + lane
__device__ float4 g_keff[B_ * CIN];

// ---------------------------------------------------------------------------
// Prologue: grid=(8,8), block=(64,8). Triggers PDL completion early.
// ---------------------------------------------------------------------------
__global__ void build_keff_kernel(const float* __restrict__ w,
                                  const float* __restrict__ affine_w,
                                  const float* __restrict__ affine_b,
                                  const float* __restrict__ k2d)
{
    const int b  = blockIdx.x;
    const int c  = blockIdx.y * 64 + threadIdx.x;
    const int js = threadIdx.y;                    // 0..7

    __shared__ float ws[WDIM];
    __shared__ float part[7][64];

    const int tid = threadIdx.y * 64 + threadIdx.x;
    if (tid < WDIM) ws[tid] = w[b * WDIM + tid];
    __syncthreads();

    float s = 0.f;
    const int j0 = js * 16;
    #pragma unroll
    for (int j = j0; j < j0 + 16; j++)
        s = fmaf(ws[j], affine_w[j * CIN + c], s);

    if (js > 0) part[js - 1][threadIdx.x] = s;
    __syncthreads();

    if (js == 0) {
        #pragma unroll
        for (int q = 0; q < 7; q++) s += part[q][threadIdx.x];
        s = (s + affine_b[c]) * INV_SQRT_CIN;
        float4 kk = *reinterpret_cast<const float4*>(k2d + c * COUT);
        float4 o;
        o.x = s * kk.x; o.y = s * kk.y; o.z = s * kk.z; o.w = s * kk.w;
        const int i = c >> 7, r = c & 127, lane = r >> 2, jj = r & 3;
        g_keff[b * CIN + (i * 4 + jj) * 32 + lane] = o;
    }

#if __CUDA_ARCH__ >= 900
    cudaTriggerProgrammaticLaunchCompletion();
#endif
}

// ---------------------------------------------------------------------------
// helpers
// ---------------------------------------------------------------------------
__device__ __forceinline__ u64 pack_f32x2(float lo, float hi) {
    u64 r;
    asm("mov.b64 %0, {%1, %2};" : "=l"(r) : "f"(lo), "f"(hi));
    return r;
}
__device__ __forceinline__ void unpack_f32x2(float& lo, float& hi, u64 v) {
    asm("mov.b64 {%0, %1}, %2;" : "=f"(lo), "=f"(hi) : "l"(v));
}
__device__ __forceinline__ u64 fma_f32x2(u64 a, u64 b, u64 c) {
    u64 d;
    asm("fma.rn.f32x2 %0, %1, %2, %3;" : "=l"(d) : "l"(a), "l"(b), "l"(c));
    return d;
}
__device__ __forceinline__ float tanh_fast(float x) {
    float r;
    asm("tanh.approx.f32 %0, %1;" : "=f"(r) : "f"(x));
    return r;
}
__device__ __forceinline__ void prefetch_l2(const void* p) {
    asm volatile("prefetch.global.L2 [%0];" :: "l"(p));
}

// packed pair reduction: two independent sums, one shuffle
__device__ __forceinline__ float pairstep(float a, float b, bool lo, int off)
{
    float send = lo ? b : a;
    float recv = __shfl_xor_sync(0xffffffffu, send, off);
    return (lo ? a : b) + recv;
}

// ---------------------------------------------------------------------------
// Main: grid=(74, 8), block=256 (8 warps), 4 CTAs/SM — one wave.
// PDL: unit-0 register loads + unit-1 L2 prefetch + bias load all BEFORE
// cudaGridDependencySynchronize().
// ---------------------------------------------------------------------------
__global__ void __launch_bounds__(256, 4)
torgb_main_kernel(const float* __restrict__ x,
                  const float* __restrict__ bias,
                  float* __restrict__ out)
{
    const int b    = blockIdx.y;
    const int warp = threadIdx.x >> 5;
    const int lane = threadIdx.x & 31;

    __shared__ __align__(16) float4 kws[CIN];   // 8 KB

    // ---- pointer setup (independent of keff) ----
    const int   p_off  = (lane >> 4) & 1;
    const int   o_idx  = (((lane >> 2) & 1) << 1) | ((lane >> 3) & 1);
    const bool  storer = (lane & 3) == 0;
    const bool  lo16 = lane < 16;
    const bool  lo8  = (lane & 8) == 0;
    const bool  lo4  = (lane & 4) == 0;

    const long long px0 = (long long)b * PIX + (long long)blockIdx.x * UNIT_PX + warp * 2;
    const float4* xp = reinterpret_cast<const float4*>(x + px0 * CIN) + lane;
    float*        op = out + px0 * COUT + p_off * COUT + o_idx;

    const long long xstep = (long long)GRID_X * UNIT_PX * (CIN / 4);
    const long long ostep = (long long)GRID_X * UNIT_PX * COUT;

    // ---- pre-sync: unit-0 register preload (independent of prologue) ----
    float4 a[4], c4[4];
    #pragma unroll
    for (int i = 0; i < 4; i++) a[i]  = __ldcs(xp + i * 32);
    #pragma unroll
    for (int i = 0; i < 4; i++) c4[i] = __ldcs(xp + 128 + i * 32);

    // ---- pre-sync: L2 prefetch of unit 1 only (tuned overlap depth) ----
    if (blockIdx.x + GRID_X < UNITS_PER_BATCH) {
        const float4* xn = xp + xstep;
        #pragma unroll
        for (int i = 0; i < 4; i++) { prefetch_l2(xn + i * 32); prefetch_l2(xn + 128 + i * 32); }
    }

    // ---- pre-sync: bias (independent of prologue) ----
    const float mybias = bias[o_idx];

    // ---- wait for prologue's g_keff writes, then stage keff in smem ----
#if __CUDA_ARCH__ >= 900
    cudaGridDependencySynchronize();
#endif
    {
        const float4* gk = g_keff + b * CIN;
        kws[threadIdx.x]       = gk[threadIdx.x];
        kws[threadIdx.x + 256] = gk[threadIdx.x + 256];
    }
    __syncthreads();

    const ulonglong2* kwl2 = reinterpret_cast<const ulonglong2*>(kws) + lane;

    int u = blockIdx.x;
    #pragma unroll 1
    while (true) {
        // ---- FMA phase: consume preloaded a/c4 (f32x2 packed) ----
        u64 p0a = 0ull, p0b = 0ull, p1a = 0ull, p1b = 0ull;

        #pragma unroll
        for (int i = 0; i < 4; i++) {
            const float av[4] = {a[i].x,  a[i].y,  a[i].z,  a[i].w};
            const float cv[4] = {c4[i].x, c4[i].y, c4[i].z, c4[i].w};
            u64 ap[4], cp[4];
            #pragma unroll
            for (int j = 0; j < 4; j++) {
                ap[j] = pack_f32x2(av[j], av[j]);
                cp[j] = pack_f32x2(cv[j], cv[j]);
            }
            #pragma unroll
            for (int j = 0; j < 4; j++) {
                const ulonglong2 kk = kwl2[(i * 4 + j) * 32];   // LDS.128
                p0a = fma_f32x2(ap[j], kk.x, p0a);
                p0b = fma_f32x2(ap[j], kk.y, p0b);
                p1a = fma_f32x2(cp[j], kk.x, p1a);
                p1b = fma_f32x2(cp[j], kk.y, p1b);
            }
        }

        // ---- rotation: next unit's loads before the reduce chain ----
        const bool more = (u + GRID_X) < UNITS_PER_BATCH;
        xp += xstep;
        if (more) {
            #pragma unroll
            for (int i = 0; i < 4; i++) a[i]  = __ldcs(xp + i * 32);
            #pragma unroll
            for (int i = 0; i < 4; i++) c4[i] = __ldcs(xp + 128 + i * 32);
        }

        float v0, v1, v2, v3, v4, v5, v6, v7;
        unpack_f32x2(v0, v1, p0a);
        unpack_f32x2(v2, v3, p0b);
        unpack_f32x2(v4, v5, p1a);
        unpack_f32x2(v6, v7, p1b);

        // ---- packed butterfly: 8 sums in 9 shuffles (verified) ----
        float r0 = pairstep(v0, v4, lo16, 16);
        float r1 = pairstep(v1, v5, lo16, 16);
        float r2 = pairstep(v2, v6, lo16, 16);
        float r3 = pairstep(v3, v7, lo16, 16);

        float s0 = pairstep(r0, r1, lo8, 8);
        float s1 = pairstep(r2, r3, lo8, 8);

        float t  = pairstep(s0, s1, lo4, 4);
        t += __shfl_xor_sync(0xffffffffu, t, 2);
        t += __shfl_xor_sync(0xffffffffu, t, 1);

        if (storer)
            *op = tanh_fast(t + mybias);

        if (!more) break;
        op += ostep;
        u  += GRID_X;
    }
}

// ---------------------------------------------------------------------------
// inputs: x[8,128,128,512], w[8,128], affine_w[128,512], affine_b[512],
//         kernel[1,1,512,4], bias[4]  -> out[8,128,128,4] f32
// ---------------------------------------------------------------------------
extern "C" void kernel_launch(void* const* d_in, const int* in_sizes, int n_in,
                              void* d_out, int out_size)
{
    const float* x        = (const float*)d_in[0];
    const float* w        = (const float*)d_in[1];
    const float* affine_w = (const float*)d_in[2];
    const float* affine_b = (const float*)d_in[3];
    const float* k2d      = (const float*)d_in[4];
    const float* bias     = (const float*)d_in[5];
    float*       out      = (float*)d_out;

    dim3 pgrid(B_, 8), pblock(64, 8);
    build_keff_kernel<<<pgrid, pblock>>>(w, affine_w, affine_b, k2d);

    // main kernel with programmatic dependent launch (overlaps prologue tail)
    cudaLaunchConfig_t cfg = {};
    cfg.gridDim  = dim3(GRID_X, B_);
    cfg.blockDim = dim3(256);
    cfg.dynamicSmemBytes = 0;
    cfg.stream = 0;
    cudaLaunchAttribute at[1];
    at[0].id = cudaLaunchAttributeProgrammaticStreamSerialization;
    at[0].val.programmaticStreamSerializationAllowed = 1;
    cfg.attrs = at;
    cfg.numAttrs = 1;
    cudaLaunchKernelEx(&cfg, torgb_main_kernel, x, bias, out);
}